// round 1
// baseline (speedup 1.0000x reference)
#include <cuda_runtime.h>
#include <math.h>

#define QLEN 1024
#define MLEN 1024
#define KLEN 2048
#define RLEN 2048
#define BSZ  2
#define DM   1024
#define NH   16
#define DH   64
#define NHD  1024   // NH*DH

// -------------------- scratch (device globals; no cudaMalloc allowed) ------
__device__ float g_qh[QLEN * BSZ * NHD];           // [i][b][n*64+d] row=(i*2+b)   8 MB
__device__ float g_kv[KLEN * BSZ * 2 * NHD];       // [k][b][2048]                32 MB
__device__ float g_rk[RLEN * NHD];                 // [j][n*64+d]                  8 MB
__device__ float g_sc[(size_t)BSZ * NH * QLEN * KLEN]; // AC, then P in-place   256 MB
__device__ float g_bd[(size_t)BSZ * NH * QLEN * RLEN]; // BD                    256 MB
__device__ float g_av[QLEN * BSZ * NHD];           // attn_vec [i][b][n*64+d]      8 MB

// -------------------- generic SGEMM: C[M,N] = A[M,K] @ B[K,N] --------------
// 64x64 block tile, BK=16, 256 threads, 4x4 per-thread register tile.
__global__ __launch_bounds__(256) void sgemm64(
    const float* __restrict__ A, const float* __restrict__ B,
    float* __restrict__ C, int M, int N, int K)
{
    __shared__ float As[16][65];   // [k][m], padded
    __shared__ float Bs[16][64];   // [k][n]
    const int tid = threadIdx.x;
    const int tx = tid & 15, ty = tid >> 4;
    const int row0 = blockIdx.y * 64, col0 = blockIdx.x * 64;

    float acc[4][4] = {};

    for (int k0 = 0; k0 < K; k0 += 16) {
        #pragma unroll
        for (int l = 0; l < 4; l++) {
            int idx = tid + l * 256;
            int m  = idx >> 4, kk = idx & 15;
            As[kk][m] = A[(size_t)(row0 + m) * K + k0 + kk];
            int kb = idx >> 6, nb = idx & 63;
            Bs[kb][nb] = B[(size_t)(k0 + kb) * N + col0 + nb];
        }
        __syncthreads();
        #pragma unroll
        for (int kk = 0; kk < 16; kk++) {
            float a[4], bb[4];
            #pragma unroll
            for (int i = 0; i < 4; i++) a[i]  = As[kk][ty + 16 * i];
            #pragma unroll
            for (int j = 0; j < 4; j++) bb[j] = Bs[kk][tx + 16 * j];
            #pragma unroll
            for (int i = 0; i < 4; i++)
                #pragma unroll
                for (int j = 0; j < 4; j++) acc[i][j] += a[i] * bb[j];
        }
        __syncthreads();
    }
    #pragma unroll
    for (int i = 0; i < 4; i++)
        #pragma unroll
        for (int j = 0; j < 4; j++)
            C[(size_t)(row0 + ty + 16 * i) * N + col0 + tx + 16 * j] = acc[i][j];
}

// -------------------- batched score GEMM (K=64), fused bias add ------------
// out[bn][i][j] = sum_d (qh[i,b,n,d] + bias[n,d]) * key[j, (b,) n, d]
// qh element (i,b,n,d) = qh[(i*2+b)*NHD + n*64 + d]
// key base = keys + b*keyStrideB + n*64, row stride keyStrideJ.
__global__ __launch_bounds__(256) void scores_kernel(
    const float* __restrict__ qh, const float* __restrict__ keys,
    int keyStrideJ, int keyStrideB,
    const float* __restrict__ bias, float* __restrict__ out)
{
    __shared__ float Qs[64][65];
    __shared__ float Ks[64][65];
    const int bn = blockIdx.z;
    const int b = bn >> 4, n = bn & 15;
    const int j0 = blockIdx.x * 64, i0 = blockIdx.y * 64;
    const int tid = threadIdx.x;
    const int tx = tid & 15, ty = tid >> 4;

    const float* kbase = keys + (size_t)b * keyStrideB + n * DH;

    #pragma unroll
    for (int l = 0; l < 16; l++) {
        int idx = tid + l * 256;
        int m = idx >> 6, d = idx & 63;
        Qs[m][d] = qh[(size_t)((i0 + m) * 2 + b) * NHD + n * DH + d] + bias[n * DH + d];
        Ks[m][d] = kbase[(size_t)(j0 + m) * keyStrideJ + d];
    }
    __syncthreads();

    float acc[4][4] = {};
    #pragma unroll 8
    for (int d = 0; d < 64; d++) {
        float a[4], kk[4];
        #pragma unroll
        for (int i = 0; i < 4; i++) a[i]  = Qs[ty + 16 * i][d];
        #pragma unroll
        for (int j = 0; j < 4; j++) kk[j] = Ks[tx + 16 * j][d];
        #pragma unroll
        for (int i = 0; i < 4; i++)
            #pragma unroll
            for (int j = 0; j < 4; j++) acc[i][j] += a[i] * kk[j];
    }

    float* ob = out + ((size_t)bn * QLEN + i0) * KLEN + j0;
    #pragma unroll
    for (int i = 0; i < 4; i++)
        #pragma unroll
        for (int j = 0; j < 4; j++)
            ob[(size_t)(ty + 16 * i) * KLEN + tx + 16 * j] = acc[i][j];
}

// -------------------- softmax with fused rel_shift gather ------------------
// s[j] = (AC[bn,i,j] + shiftedBD(i,j)) * scale; P written in-place over AC.
// shiftedBD(i,j): L = i*KLEN + j + QLEN; i2 = L/(KLEN+1); j2 = L%(KLEN+1);
//                 value = (j2==0) ? 0 : BD[bn, i2, j2-1]
__global__ __launch_bounds__(256) void softmax_kernel(
    float* __restrict__ sc, const float* __restrict__ bd)
{
    const int i  = blockIdx.x;
    const int bn = blockIdx.y;
    const int tid = threadIdx.x;
    float* row = sc + ((size_t)bn * QLEN + i) * KLEN;
    const float* bdb = bd + (size_t)bn * QLEN * RLEN;

    __shared__ float red[256];

    float vals[8];
    float mx = -3.402823466e38f;
    #pragma unroll
    for (int l = 0; l < 8; l++) {
        int j = tid + l * 256;
        long L = (long)i * KLEN + j + QLEN;
        int i2 = (int)(L / (KLEN + 1));
        int j2 = (int)(L - (long)i2 * (KLEN + 1));
        float bdv = (j2 == 0) ? 0.0f : bdb[(size_t)i2 * RLEN + (j2 - 1)];
        float s = (row[j] + bdv) * 0.125f;   // 1/sqrt(64)
        vals[l] = s;
        mx = fmaxf(mx, s);
    }
    red[tid] = mx; __syncthreads();
    for (int s = 128; s > 0; s >>= 1) {
        if (tid < s) red[tid] = fmaxf(red[tid], red[tid + s]);
        __syncthreads();
    }
    mx = red[0]; __syncthreads();

    float sum = 0.0f;
    #pragma unroll
    for (int l = 0; l < 8; l++) {
        vals[l] = __expf(vals[l] - mx);
        sum += vals[l];
    }
    red[tid] = sum; __syncthreads();
    for (int s = 128; s > 0; s >>= 1) {
        if (tid < s) red[tid] += red[tid + s];
        __syncthreads();
    }
    float inv = 1.0f / red[0];

    #pragma unroll
    for (int l = 0; l < 8; l++)
        row[tid + l * 256] = vals[l] * inv;
}

// -------------------- P @ V batched: av[i,b,n,d] = sum_j P[bn,i,j] V[j,b,n,d]
__global__ __launch_bounds__(256) void pv_kernel(
    const float* __restrict__ P, const float* __restrict__ kv,
    float* __restrict__ av)
{
    __shared__ float Ps[16][65];
    __shared__ float Vs[16][64];
    const int bn = blockIdx.y;
    const int b = bn >> 4, n = bn & 15;
    const int i0 = blockIdx.x * 64;
    const int tid = threadIdx.x;
    const int tx = tid & 15, ty = tid >> 4;

    const float* Pb = P + (size_t)bn * QLEN * KLEN;
    const float* Vb = kv + (size_t)b * 2 * NHD + NHD + n * DH;  // row stride 4096

    float acc[4][4] = {};
    for (int k0 = 0; k0 < KLEN; k0 += 16) {
        #pragma unroll
        for (int l = 0; l < 4; l++) {
            int idx = tid + l * 256;
            int m = idx >> 4, kk = idx & 15;
            Ps[kk][m] = Pb[(size_t)(i0 + m) * KLEN + k0 + kk];
            int kb = idx >> 6, nb = idx & 63;
            Vs[kb][nb] = Vb[(size_t)(k0 + kb) * (2 * 2 * NHD) + nb];
        }
        __syncthreads();
        #pragma unroll
        for (int kk = 0; kk < 16; kk++) {
            float a[4], v[4];
            #pragma unroll
            for (int i = 0; i < 4; i++) a[i] = Ps[kk][ty + 16 * i];
            #pragma unroll
            for (int j = 0; j < 4; j++) v[j] = Vs[kk][tx + 16 * j];
            #pragma unroll
            for (int i = 0; i < 4; i++)
                #pragma unroll
                for (int j = 0; j < 4; j++) acc[i][j] += a[i] * v[j];
        }
        __syncthreads();
    }
    #pragma unroll
    for (int i = 0; i < 4; i++)
        #pragma unroll
        for (int j = 0; j < 4; j++)
            av[(size_t)((i0 + ty + 16 * i) * 2 + b) * NHD + n * DH + tx + 16 * j] = acc[i][j];
}

// ---------------------------------------------------------------------------
extern "C" void kernel_launch(void* const* d_in, const int* in_sizes, int n_in,
                              void* d_out, int out_size)
{
    const float* w   = (const float*)d_in[0];  // [2048, 2, 1024]
    const float* r   = (const float*)d_in[1];  // [2048, 1024]
    const float* rwb = (const float*)d_in[2];  // [16, 64]
    const float* rrb = (const float*)d_in[3];  // [16, 64]
    const float* Wq  = (const float*)d_in[4];  // [1024, 1024]
    const float* Wkv = (const float*)d_in[5];  // [1024, 2048]
    const float* Wr  = (const float*)d_in[6];  // [1024, 1024]
    const float* Wo  = (const float*)d_in[7];  // [1024, 1024]
    float* out = (float*)d_out;                // [1024, 2, 1024]

    float *qh, *kv, *rk, *sc, *bd, *av;
    cudaGetSymbolAddress((void**)&qh, g_qh);
    cudaGetSymbolAddress((void**)&kv, g_kv);
    cudaGetSymbolAddress((void**)&rk, g_rk);
    cudaGetSymbolAddress((void**)&sc, g_sc);
    cudaGetSymbolAddress((void**)&bd, g_bd);
    cudaGetSymbolAddress((void**)&av, g_av);

    // 1) q heads: (w[1024:]) [2048,1024] @ Wq [1024,1024] -> qh [2048,1024]
    sgemm64<<<dim3(1024 / 64, 2048 / 64), 256>>>(
        w + (size_t)QLEN * BSZ * DM, Wq, qh, 2048, 1024, 1024);

    // 2) kv: w [4096,1024] @ Wkv [1024,2048] -> kv [4096,2048]
    sgemm64<<<dim3(2048 / 64, 4096 / 64), 256>>>(w, Wkv, kv, 4096, 2048, 1024);

    // 3) r heads: r [2048,1024] @ Wr [1024,1024] -> rk [2048,1024]
    sgemm64<<<dim3(1024 / 64, 2048 / 64), 256>>>(r, Wr, rk, 2048, 1024, 1024);

    // 4a) AC: keys = K-heads in kv (base b*2048 + n*64, row stride 4096)
    scores_kernel<<<dim3(KLEN / 64, QLEN / 64, 32), 256>>>(
        qh, kv, 2 * 2 * NHD, 2 * NHD, rwb, sc);

    // 4b) BD: keys = rk (base n*64, row stride 1024)
    scores_kernel<<<dim3(RLEN / 64, QLEN / 64, 32), 256>>>(
        qh, rk, NHD, 0, rrb, bd);

    // 4c) softmax with fused rel_shift (P overwrites AC buffer)
    softmax_kernel<<<dim3(QLEN, 32), 256>>>(sc, bd);

    // 4d) attn_vec = P @ V
    pv_kernel<<<dim3(QLEN / 64, 32), 256>>>(sc, kv, av);

    // 5) out = attn_vec [2048,1024] @ Wo [1024,1024]
    sgemm64<<<dim3(1024 / 64, 2048 / 64), 256>>>(av, Wo, out, 2048, 1024, 1024);
}

// round 2
// speedup vs baseline: 2.3164x; 2.3164x over previous
#include <cuda_runtime.h>
#include <math.h>
#include <stdint.h>

#define QLEN 1024
#define KLEN 2048
#define RLEN 2048
#define BSZ  2
#define DM   1024
#define NH   16
#define DH   64
#define NHD  1024   // NH*DH

// -------------------- scratch (device globals) ------------------------------
__device__ float g_qh[QLEN * BSZ * NHD];               // rows (i*2+b), 1024 wide
__device__ float g_kv[KLEN * BSZ * 2 * NHD];           // rows (k*2+b), 2048 wide
__device__ float g_rk[RLEN * NHD];                     // rows j, 1024 wide
__device__ float g_sc[(size_t)BSZ * NH * QLEN * KLEN]; // AC, then P in-place
__device__ float g_bd[(size_t)BSZ * NH * QLEN * RLEN]; // BD
__device__ float g_av[QLEN * BSZ * NHD];               // attn_vec rows (i*2+b)

// -------------------- tf32 helpers ------------------------------------------
__device__ __forceinline__ uint32_t f2tf(float x) {
    uint32_t r;
    asm("cvt.rna.tf32.f32 %0, %1;" : "=r"(r) : "f"(x));
    return r;
}

__device__ __forceinline__ void mma8(float* d, const uint32_t* a, const uint32_t* b) {
    asm volatile(
        "mma.sync.aligned.m16n8k8.row.col.f32.tf32.tf32.f32 "
        "{%0,%1,%2,%3},{%4,%5,%6,%7},{%8,%9},{%0,%1,%2,%3};\n"
        : "+f"(d[0]), "+f"(d[1]), "+f"(d[2]), "+f"(d[3])
        : "r"(a[0]), "r"(a[1]), "r"(a[2]), "r"(a[3]), "r"(b[0]), "r"(b[1]));
}

// -------------------- generic tf32 GEMM: C[M,N] = A[M,K] @ B[K,N] -----------
// Block tile 128x128, BK=16, 256 threads = 8 warps (2x4), warp tile 64x32.
__global__ __launch_bounds__(256) void gemm_tf32(
    const float* __restrict__ A, const float* __restrict__ B,
    float* __restrict__ C, int M, int N, int K)
{
    __shared__ uint32_t As[128][20];   // [m][k] pad 4: a-frag conflict-free
    __shared__ uint32_t Bs[16][136];   // [k][n] pad 8: b-frag conflict-free
    const int tid  = threadIdx.x;
    const int lane = tid & 31;
    const int warp = tid >> 5;
    const int wm = (warp >> 2) * 64;
    const int wn = (warp & 3) * 32;
    const int row0 = blockIdx.y * 128, col0 = blockIdx.x * 128;

    float acc[4][4][4];
    #pragma unroll
    for (int i = 0; i < 4; i++)
        #pragma unroll
        for (int j = 0; j < 4; j++)
            #pragma unroll
            for (int r = 0; r < 4; r++) acc[i][j][r] = 0.0f;

    const int am = tid >> 1, aks = (tid & 1) * 8;
    const int bk = tid >> 4, bns = (tid & 15) * 8;

    for (int k0 = 0; k0 < K; k0 += 16) {
        // stage A tile (convert to tf32 once here)
        const float4* ap = (const float4*)(A + (size_t)(row0 + am) * K + k0 + aks);
        float4 a0 = ap[0], a1 = ap[1];
        uint4 ua0 = make_uint4(f2tf(a0.x), f2tf(a0.y), f2tf(a0.z), f2tf(a0.w));
        uint4 ua1 = make_uint4(f2tf(a1.x), f2tf(a1.y), f2tf(a1.z), f2tf(a1.w));
        *(uint4*)&As[am][aks]     = ua0;
        *(uint4*)&As[am][aks + 4] = ua1;
        // stage B tile
        const float4* bp = (const float4*)(B + (size_t)(k0 + bk) * N + col0 + bns);
        float4 b0 = bp[0], b1 = bp[1];
        uint4 ub0 = make_uint4(f2tf(b0.x), f2tf(b0.y), f2tf(b0.z), f2tf(b0.w));
        uint4 ub1 = make_uint4(f2tf(b1.x), f2tf(b1.y), f2tf(b1.z), f2tf(b1.w));
        *(uint4*)&Bs[bk][bns]     = ub0;
        *(uint4*)&Bs[bk][bns + 4] = ub1;
        __syncthreads();

        #pragma unroll
        for (int kk = 0; kk < 16; kk += 8) {
            uint32_t af[4][4];
            #pragma unroll
            for (int mt = 0; mt < 4; mt++) {
                int r = wm + mt * 16 + (lane >> 2);
                int c = kk + (lane & 3);
                af[mt][0] = As[r][c];
                af[mt][1] = As[r + 8][c];
                af[mt][2] = As[r][c + 4];
                af[mt][3] = As[r + 8][c + 4];
            }
            #pragma unroll
            for (int nt = 0; nt < 4; nt++) {
                uint32_t bf[2];
                int n = wn + nt * 8 + (lane >> 2);
                bf[0] = Bs[kk + (lane & 3)][n];
                bf[1] = Bs[kk + 4 + (lane & 3)][n];
                #pragma unroll
                for (int mt = 0; mt < 4; mt++) mma8(acc[mt][nt], af[mt], bf);
            }
        }
        __syncthreads();
    }

    #pragma unroll
    for (int mt = 0; mt < 4; mt++)
        #pragma unroll
        for (int nt = 0; nt < 4; nt++) {
            int r = row0 + wm + mt * 16 + (lane >> 2);
            int c = col0 + wn + nt * 8 + 2 * (lane & 3);
            *(float2*)&C[(size_t)r * N + c]       = make_float2(acc[mt][nt][0], acc[mt][nt][1]);
            *(float2*)&C[(size_t)(r + 8) * N + c] = make_float2(acc[mt][nt][2], acc[mt][nt][3]);
        }
}

// -------------------- batched scores (tf32), K=64, fused bias ---------------
// out[bn][i][j] = sum_d (qh[i,b,n,d]+bias[n,d]) * key[j,(b,)n,d]
// Block tile 128(i) x 128(j), 8 warps 2x4. Dynamic SMEM: Qs[128][68], Ks[128][68].
extern __shared__ uint32_t s_dyn[];
__global__ __launch_bounds__(256) void scores_tf32(
    const float* __restrict__ qh, const float* __restrict__ keys,
    int strideJ, int strideB,
    const float* __restrict__ bias, float* __restrict__ out)
{
    uint32_t (*Qs)[68] = (uint32_t(*)[68])s_dyn;
    uint32_t (*Ks)[68] = (uint32_t(*)[68])(s_dyn + 128 * 68);

    const int bn = blockIdx.z;
    const int b = bn >> 4, n = bn & 15;
    const int j0 = blockIdx.x * 128, i0 = blockIdx.y * 128;
    const int tid  = threadIdx.x;
    const int lane = tid & 31;
    const int warp = tid >> 5;
    const int wm = (warp >> 2) * 64;   // i
    const int wn = (warp & 3) * 32;    // j

    // loads: thread covers one half-row (32 floats) of Q and K tiles
    const int m = tid >> 1, half = (tid & 1) * 32;
    const float* qrow = qh + (size_t)((i0 + m) * 2 + b) * NHD + n * DH + half;
    const float* krow = keys + (size_t)b * strideB + (size_t)(j0 + m) * strideJ + n * DH + half;
    const float4* bias4 = (const float4*)(bias + n * DH + half);

    #pragma unroll
    for (int q = 0; q < 8; q++) {
        float4 qv = ((const float4*)qrow)[q];
        float4 bv = bias4[q];
        int d = half + q * 4;
        *(uint4*)&Qs[m][d] = make_uint4(f2tf(qv.x + bv.x), f2tf(qv.y + bv.y),
                                        f2tf(qv.z + bv.z), f2tf(qv.w + bv.w));
        float4 kv4 = ((const float4*)krow)[q];
        *(uint4*)&Ks[m][d] = make_uint4(f2tf(kv4.x), f2tf(kv4.y), f2tf(kv4.z), f2tf(kv4.w));
    }
    __syncthreads();

    float acc[4][4][4];
    #pragma unroll
    for (int i = 0; i < 4; i++)
        #pragma unroll
        for (int j = 0; j < 4; j++)
            #pragma unroll
            for (int r = 0; r < 4; r++) acc[i][j][r] = 0.0f;

    #pragma unroll
    for (int kk = 0; kk < 64; kk += 8) {
        uint32_t af[4][4];
        #pragma unroll
        for (int mt = 0; mt < 4; mt++) {
            int r = wm + mt * 16 + (lane >> 2);
            int c = kk + (lane & 3);
            af[mt][0] = Qs[r][c];
            af[mt][1] = Qs[r + 8][c];
            af[mt][2] = Qs[r][c + 4];
            af[mt][3] = Qs[r + 8][c + 4];
        }
        #pragma unroll
        for (int nt = 0; nt < 4; nt++) {
            uint32_t bf[2];
            int j = wn + nt * 8 + (lane >> 2);
            bf[0] = Ks[j][kk + (lane & 3)];
            bf[1] = Ks[j][kk + 4 + (lane & 3)];
            #pragma unroll
            for (int mt = 0; mt < 4; mt++) mma8(acc[mt][nt], af[mt], bf);
        }
    }

    float* ob = out + ((size_t)bn * QLEN) * KLEN;
    #pragma unroll
    for (int mt = 0; mt < 4; mt++)
        #pragma unroll
        for (int nt = 0; nt < 4; nt++) {
            int r = i0 + wm + mt * 16 + (lane >> 2);
            int c = j0 + wn + nt * 8 + 2 * (lane & 3);
            *(float2*)&ob[(size_t)r * KLEN + c]       = make_float2(acc[mt][nt][0], acc[mt][nt][1]);
            *(float2*)&ob[(size_t)(r + 8) * KLEN + c] = make_float2(acc[mt][nt][2], acc[mt][nt][3]);
        }
}

// -------------------- softmax with fused rel_shift gather -------------------
__global__ __launch_bounds__(256) void softmax_kernel(
    float* __restrict__ sc, const float* __restrict__ bd)
{
    const int i  = blockIdx.x;
    const int bn = blockIdx.y;
    const int tid = threadIdx.x;
    float* row = sc + ((size_t)bn * QLEN + i) * KLEN;
    const float* bdb = bd + (size_t)bn * QLEN * RLEN;

    __shared__ float red[256];

    float vals[8];
    float mx = -3.402823466e38f;
    #pragma unroll
    for (int l = 0; l < 8; l++) {
        int j = tid + l * 256;
        long L = (long)i * KLEN + j + QLEN;
        int i2 = (int)(L / (KLEN + 1));
        int j2 = (int)(L - (long)i2 * (KLEN + 1));
        float bdv = (j2 == 0) ? 0.0f : bdb[(size_t)i2 * RLEN + (j2 - 1)];
        float s = (row[j] + bdv) * 0.125f;
        vals[l] = s;
        mx = fmaxf(mx, s);
    }
    red[tid] = mx; __syncthreads();
    for (int s = 128; s > 0; s >>= 1) {
        if (tid < s) red[tid] = fmaxf(red[tid], red[tid + s]);
        __syncthreads();
    }
    mx = red[0]; __syncthreads();

    float sum = 0.0f;
    #pragma unroll
    for (int l = 0; l < 8; l++) {
        vals[l] = __expf(vals[l] - mx);
        sum += vals[l];
    }
    red[tid] = sum; __syncthreads();
    for (int s = 128; s > 0; s >>= 1) {
        if (tid < s) red[tid] += red[tid + s];
        __syncthreads();
    }
    float inv = 1.0f / red[0];

    #pragma unroll
    for (int l = 0; l < 8; l++)
        row[tid + l * 256] = vals[l] * inv;
}

// -------------------- P @ V batched (tf32) ----------------------------------
// av[i,b,n,d] = sum_j P[bn,i,j] * V[j,b,n,d].  Block tile 128(i) x 64(d), BK=32.
// 8 warps 4x2, warp tile 32x32.
__global__ __launch_bounds__(256) void pv_tf32(
    const float* __restrict__ P, const float* __restrict__ kv,
    float* __restrict__ av)
{
    __shared__ uint32_t Ps[128][36];   // [i][j] pad 4
    __shared__ uint32_t Vs[32][72];    // [j][d] pad 8
    const int bn = blockIdx.y;
    const int b = bn >> 4, n = bn & 15;
    const int i0 = blockIdx.x * 128;
    const int tid  = threadIdx.x;
    const int lane = tid & 31;
    const int warp = tid >> 5;
    const int wm = (warp >> 1) * 32;   // i
    const int wn = (warp & 1) * 32;    // d

    const float* Pb = P + (size_t)bn * QLEN * KLEN;
    const float* Vb = kv + (size_t)b * 2 * NHD + NHD + n * DH;  // stride 4096/j

    float acc[2][4][4];
    #pragma unroll
    for (int i = 0; i < 2; i++)
        #pragma unroll
        for (int j = 0; j < 4; j++)
            #pragma unroll
            for (int r = 0; r < 4; r++) acc[i][j][r] = 0.0f;

    const int pm = tid >> 1, pks = (tid & 1) * 16;
    const int vk = tid >> 3, vns = (tid & 7) * 8;

    for (int k0 = 0; k0 < KLEN; k0 += 32) {
        const float4* pp = (const float4*)(Pb + (size_t)(i0 + pm) * KLEN + k0 + pks);
        #pragma unroll
        for (int q = 0; q < 4; q++) {
            float4 v = pp[q];
            *(uint4*)&Ps[pm][pks + q * 4] =
                make_uint4(f2tf(v.x), f2tf(v.y), f2tf(v.z), f2tf(v.w));
        }
        const float4* vp = (const float4*)(Vb + (size_t)(k0 + vk) * (BSZ * 2 * NHD) + vns);
        float4 v0 = vp[0], v1 = vp[1];
        *(uint4*)&Vs[vk][vns]     = make_uint4(f2tf(v0.x), f2tf(v0.y), f2tf(v0.z), f2tf(v0.w));
        *(uint4*)&Vs[vk][vns + 4] = make_uint4(f2tf(v1.x), f2tf(v1.y), f2tf(v1.z), f2tf(v1.w));
        __syncthreads();

        #pragma unroll
        for (int kk = 0; kk < 32; kk += 8) {
            uint32_t af[2][4];
            #pragma unroll
            for (int mt = 0; mt < 2; mt++) {
                int r = wm + mt * 16 + (lane >> 2);
                int c = kk + (lane & 3);
                af[mt][0] = Ps[r][c];
                af[mt][1] = Ps[r + 8][c];
                af[mt][2] = Ps[r][c + 4];
                af[mt][3] = Ps[r + 8][c + 4];
            }
            #pragma unroll
            for (int nt = 0; nt < 4; nt++) {
                uint32_t bf[2];
                int d = wn + nt * 8 + (lane >> 2);
                bf[0] = Vs[kk + (lane & 3)][d];
                bf[1] = Vs[kk + 4 + (lane & 3)][d];
                #pragma unroll
                for (int mt = 0; mt < 2; mt++) mma8(acc[mt][nt], af[mt], bf);
            }
        }
        __syncthreads();
    }

    #pragma unroll
    for (int mt = 0; mt < 2; mt++)
        #pragma unroll
        for (int nt = 0; nt < 4; nt++) {
            int i = i0 + wm + mt * 16 + (lane >> 2);
            int d = n * DH + wn + nt * 8 + 2 * (lane & 3);
            *(float2*)&av[(size_t)(i * 2 + b) * NHD + d] =
                make_float2(acc[mt][nt][0], acc[mt][nt][1]);
            *(float2*)&av[(size_t)((i + 8) * 2 + b) * NHD + d] =
                make_float2(acc[mt][nt][2], acc[mt][nt][3]);
        }
}

// ---------------------------------------------------------------------------
extern "C" void kernel_launch(void* const* d_in, const int* in_sizes, int n_in,
                              void* d_out, int out_size)
{
    const float* w   = (const float*)d_in[0];
    const float* r   = (const float*)d_in[1];
    const float* rwb = (const float*)d_in[2];
    const float* rrb = (const float*)d_in[3];
    const float* Wq  = (const float*)d_in[4];
    const float* Wkv = (const float*)d_in[5];
    const float* Wr  = (const float*)d_in[6];
    const float* Wo  = (const float*)d_in[7];
    float* out = (float*)d_out;

    float *qh, *kv, *rk, *sc, *bd, *av;
    cudaGetSymbolAddress((void**)&qh, g_qh);
    cudaGetSymbolAddress((void**)&kv, g_kv);
    cudaGetSymbolAddress((void**)&rk, g_rk);
    cudaGetSymbolAddress((void**)&sc, g_sc);
    cudaGetSymbolAddress((void**)&bd, g_bd);
    cudaGetSymbolAddress((void**)&av, g_av);

    static int smem_set = 0;
    if (!smem_set) {
        cudaFuncSetAttribute(scores_tf32,
                             cudaFuncAttributeMaxDynamicSharedMemorySize,
                             2 * 128 * 68 * 4);
        smem_set = 1;
    }
    const int score_smem = 2 * 128 * 68 * 4;

    // 1) q heads: w[-qlen:] [2048,1024] @ Wq -> qh [2048,1024]
    gemm_tf32<<<dim3(1024 / 128, 2048 / 128), 256>>>(
        w + (size_t)QLEN * BSZ * DM, Wq, qh, 2048, 1024, 1024);

    // 2) kv: w [4096,1024] @ Wkv [1024,2048] -> kv [4096,2048]
    gemm_tf32<<<dim3(2048 / 128, 4096 / 128), 256>>>(w, Wkv, kv, 4096, 2048, 1024);

    // 3) r heads: r [2048,1024] @ Wr -> rk [2048,1024]
    gemm_tf32<<<dim3(1024 / 128, 2048 / 128), 256>>>(r, Wr, rk, 2048, 1024, 1024);

    // 4a) AC
    scores_tf32<<<dim3(KLEN / 128, QLEN / 128, 32), 256, score_smem>>>(
        qh, kv, BSZ * 2 * NHD, 2 * NHD, rwb, sc);

    // 4b) BD
    scores_tf32<<<dim3(RLEN / 128, QLEN / 128, 32), 256, score_smem>>>(
        qh, rk, NHD, 0, rrb, bd);

    // 4c) softmax with fused rel_shift (P overwrites AC buffer)
    softmax_kernel<<<dim3(QLEN, 32), 256>>>(sc, bd);

    // 4d) attn_vec = P @ V
    pv_tf32<<<dim3(QLEN / 128, 32), 256>>>(sc, kv, av);

    // 5) out = attn_vec [2048,1024] @ Wo -> out
    gemm_tf32<<<dim3(1024 / 128, 2048 / 128), 256>>>(av, Wo, out, 2048, 1024, 1024);
}

// round 3
// speedup vs baseline: 2.7239x; 1.1759x over previous
#include <cuda_runtime.h>
#include <math.h>
#include <stdint.h>

#define QLEN 1024
#define KLEN 2048
#define RLEN 2048
#define BSZ  2
#define DM   1024
#define NH   16
#define DH   64
#define NHD  1024   // NH*DH

#define BDSTRIDE 2049
#define BDSZ     2098176   // per-(b,n) shifted-BD buffer: 1023*2049+2048+1

// -------------------- scratch (device globals) ------------------------------
__device__ float g_qh[QLEN * BSZ * NHD];               // rows (i*2+b), 1024 wide
__device__ float g_kv[KLEN * BSZ * 2 * NHD];           // rows (k*2+b), 2048 wide
__device__ float g_rk[RLEN * NHD];                     // rows j, 1024 wide
__device__ float g_bd[(size_t)BSZ * NH * BDSZ];        // shifted BD (stride 2049)
__device__ float g_av[QLEN * BSZ * NHD];               // attn_vec rows (i*2+b)

// -------------------- tf32 helpers ------------------------------------------
__device__ __forceinline__ uint32_t f2tf(float x) {
    uint32_t r;
    asm("cvt.rna.tf32.f32 %0, %1;" : "=r"(r) : "f"(x));
    return r;
}

__device__ __forceinline__ void mma8(float* d, const uint32_t* a, const uint32_t* b) {
    asm volatile(
        "mma.sync.aligned.m16n8k8.row.col.f32.tf32.tf32.f32 "
        "{%0,%1,%2,%3},{%4,%5,%6,%7},{%8,%9},{%0,%1,%2,%3};\n"
        : "+f"(d[0]), "+f"(d[1]), "+f"(d[2]), "+f"(d[3])
        : "r"(a[0]), "r"(a[1]), "r"(a[2]), "r"(a[3]), "r"(b[0]), "r"(b[1]));
}

// -------------------- generic tf32 GEMM: C[M,N] = A[M,K] @ B[K,N] -----------
__global__ __launch_bounds__(256) void gemm_tf32(
    const float* __restrict__ A, const float* __restrict__ B,
    float* __restrict__ C, int M, int N, int K)
{
    __shared__ uint32_t As[128][20];
    __shared__ uint32_t Bs[16][136];
    const int tid  = threadIdx.x;
    const int lane = tid & 31;
    const int warp = tid >> 5;
    const int wm = (warp >> 2) * 64;
    const int wn = (warp & 3) * 32;
    const int row0 = blockIdx.y * 128, col0 = blockIdx.x * 128;

    float acc[4][4][4];
    #pragma unroll
    for (int i = 0; i < 4; i++)
        #pragma unroll
        for (int j = 0; j < 4; j++)
            #pragma unroll
            for (int r = 0; r < 4; r++) acc[i][j][r] = 0.0f;

    const int am = tid >> 1, aks = (tid & 1) * 8;
    const int bk = tid >> 4, bns = (tid & 15) * 8;

    for (int k0 = 0; k0 < K; k0 += 16) {
        const float4* ap = (const float4*)(A + (size_t)(row0 + am) * K + k0 + aks);
        float4 a0 = ap[0], a1 = ap[1];
        *(uint4*)&As[am][aks]     = make_uint4(f2tf(a0.x), f2tf(a0.y), f2tf(a0.z), f2tf(a0.w));
        *(uint4*)&As[am][aks + 4] = make_uint4(f2tf(a1.x), f2tf(a1.y), f2tf(a1.z), f2tf(a1.w));
        const float4* bp = (const float4*)(B + (size_t)(k0 + bk) * N + col0 + bns);
        float4 b0 = bp[0], b1 = bp[1];
        *(uint4*)&Bs[bk][bns]     = make_uint4(f2tf(b0.x), f2tf(b0.y), f2tf(b0.z), f2tf(b0.w));
        *(uint4*)&Bs[bk][bns + 4] = make_uint4(f2tf(b1.x), f2tf(b1.y), f2tf(b1.z), f2tf(b1.w));
        __syncthreads();

        #pragma unroll
        for (int kk = 0; kk < 16; kk += 8) {
            uint32_t af[4][4];
            #pragma unroll
            for (int mt = 0; mt < 4; mt++) {
                int r = wm + mt * 16 + (lane >> 2);
                int c = kk + (lane & 3);
                af[mt][0] = As[r][c];
                af[mt][1] = As[r + 8][c];
                af[mt][2] = As[r][c + 4];
                af[mt][3] = As[r + 8][c + 4];
            }
            #pragma unroll
            for (int nt = 0; nt < 4; nt++) {
                uint32_t bf[2];
                int n = wn + nt * 8 + (lane >> 2);
                bf[0] = Bs[kk + (lane & 3)][n];
                bf[1] = Bs[kk + 4 + (lane & 3)][n];
                #pragma unroll
                for (int mt = 0; mt < 4; mt++) mma8(acc[mt][nt], af[mt], bf);
            }
        }
        __syncthreads();
    }

    #pragma unroll
    for (int mt = 0; mt < 4; mt++)
        #pragma unroll
        for (int nt = 0; nt < 4; nt++) {
            int r = row0 + wm + mt * 16 + (lane >> 2);
            int c = col0 + wn + nt * 8 + 2 * (lane & 3);
            *(float2*)&C[(size_t)r * N + c]       = make_float2(acc[mt][nt][0], acc[mt][nt][1]);
            *(float2*)&C[(size_t)(r + 8) * N + c] = make_float2(acc[mt][nt][2], acc[mt][nt][3]);
        }
}

// -------------------- BD scores (tf32) -> shifted layout --------------------
// BD[i',c'] = (qh[i',b,n,:]+rrb[n,:]) . rk[c',n,:]; write to buf[i'*2049+c'+1].
extern __shared__ uint32_t s_dyn[];
__global__ __launch_bounds__(256) void scores_bd_tf32(
    const float* __restrict__ qh, const float* __restrict__ rk,
    const float* __restrict__ bias, float* __restrict__ out)
{
    uint32_t (*Qs)[68] = (uint32_t(*)[68])s_dyn;
    uint32_t (*Ks)[68] = (uint32_t(*)[68])(s_dyn + 128 * 68);

    const int bn = blockIdx.z;
    const int b = bn >> 4, n = bn & 15;
    const int j0 = blockIdx.x * 128, i0 = blockIdx.y * 128;
    const int tid  = threadIdx.x;
    const int lane = tid & 31;
    const int warp = tid >> 5;
    const int wm = (warp >> 2) * 64;
    const int wn = (warp & 3) * 32;

    const int m = tid >> 1, half = (tid & 1) * 32;
    const float* qrow = qh + (size_t)((i0 + m) * 2 + b) * NHD + n * DH + half;
    const float* krow = rk + (size_t)(j0 + m) * NHD + n * DH + half;
    const float4* bias4 = (const float4*)(bias + n * DH + half);

    #pragma unroll
    for (int q = 0; q < 8; q++) {
        float4 qv = ((const float4*)qrow)[q];
        float4 bv = bias4[q];
        int d = half + q * 4;
        *(uint4*)&Qs[m][d] = make_uint4(f2tf(qv.x + bv.x), f2tf(qv.y + bv.y),
                                        f2tf(qv.z + bv.z), f2tf(qv.w + bv.w));
        float4 kv4 = ((const float4*)krow)[q];
        *(uint4*)&Ks[m][d] = make_uint4(f2tf(kv4.x), f2tf(kv4.y), f2tf(kv4.z), f2tf(kv4.w));
    }
    __syncthreads();

    float acc[4][4][4];
    #pragma unroll
    for (int i = 0; i < 4; i++)
        #pragma unroll
        for (int j = 0; j < 4; j++)
            #pragma unroll
            for (int r = 0; r < 4; r++) acc[i][j][r] = 0.0f;

    #pragma unroll
    for (int kk = 0; kk < 64; kk += 8) {
        uint32_t af[4][4];
        #pragma unroll
        for (int mt = 0; mt < 4; mt++) {
            int r = wm + mt * 16 + (lane >> 2);
            int c = kk + (lane & 3);
            af[mt][0] = Qs[r][c];
            af[mt][1] = Qs[r + 8][c];
            af[mt][2] = Qs[r][c + 4];
            af[mt][3] = Qs[r + 8][c + 4];
        }
        #pragma unroll
        for (int nt = 0; nt < 4; nt++) {
            uint32_t bf[2];
            int j = wn + nt * 8 + (lane >> 2);
            bf[0] = Ks[j][kk + (lane & 3)];
            bf[1] = Ks[j][kk + 4 + (lane & 3)];
            #pragma unroll
            for (int mt = 0; mt < 4; mt++) mma8(acc[mt][nt], af[mt], bf);
        }
    }

    float* ob = out + (size_t)bn * BDSZ;
    #pragma unroll
    for (int mt = 0; mt < 4; mt++)
        #pragma unroll
        for (int nt = 0; nt < 4; nt++) {
            int r = i0 + wm + mt * 16 + (lane >> 2);
            int c = j0 + wn + nt * 8 + 2 * (lane & 3);
            size_t p0 = (size_t)r * BDSTRIDE + c + 1;
            size_t p1 = (size_t)(r + 8) * BDSTRIDE + c + 1;
            ob[p0]     = acc[mt][nt][0];
            ob[p0 + 1] = acc[mt][nt][1];
            ob[p1]     = acc[mt][nt][2];
            ob[p1 + 1] = acc[mt][nt][3];
        }
}

// zero the "dropped column" positions of the shifted buffer
__global__ void zero_diag(float* __restrict__ buf) {
    int k = blockIdx.x * blockDim.x + threadIdx.x;  // 0..32*1024-1
    int bn = k >> 10, kk = k & 1023;
    if (kk >= 1)
        buf[(size_t)bn * BDSZ + (size_t)kk * BDSTRIDE] = 0.0f;
}

// -------------------- fused attention: S=(Q+b)K^T + BDshift, softmax, PV ----
// grid (QLEN/64, 32), 128 threads = 4 warps, warp = 16 q-rows.
__global__ __launch_bounds__(128, 2) void attn_fused(
    const float* __restrict__ qh, const float* __restrict__ kv,
    const float* __restrict__ bdbuf, const float* __restrict__ rwb,
    float* __restrict__ av)
{
    extern __shared__ uint32_t smem[];
    uint32_t (*Ks)[68] = (uint32_t(*)[68])smem;              // [j][d] pad->stride 68 (mod32=4)
    uint32_t (*Vs)[72] = (uint32_t(*)[72])(smem + 128 * 68); // [j][d] pad->stride 72 (mod32=8)

    const int bn = blockIdx.y;
    const int b = bn >> 4, n = bn & 15;
    const int i0 = blockIdx.x * 64;
    const int tid  = threadIdx.x;
    const int lane = tid & 31;
    const int warp = tid >> 5;
    const int row = lane >> 2;   // 0..7
    const int qd  = lane & 3;    // 0..3
    const int ir0 = i0 + warp * 16 + row;   // global q row (and ir0+8)

    // ---- Q fragments with r_w_bias folded in (register-resident) ----
    uint32_t qf[8][4];
    {
        const float* q0 = qh + (size_t)(ir0 * 2 + b) * NHD + n * DH;
        const float* q1 = q0 + 16 * NHD;   // row +8
        const float* bias = rwb + n * DH;
        #pragma unroll
        for (int g = 0; g < 8; g++) {
            int d0 = g * 8 + qd, d1 = d0 + 4;
            qf[g][0] = f2tf(q0[d0] + bias[d0]);
            qf[g][1] = f2tf(q1[d0] + bias[d0]);
            qf[g][2] = f2tf(q0[d1] + bias[d1]);
            qf[g][3] = f2tf(q1[d1] + bias[d1]);
        }
    }

    float Ov[8][4];
    #pragma unroll
    for (int dt = 0; dt < 8; dt++)
        #pragma unroll
        for (int r = 0; r < 4; r++) Ov[dt][r] = 0.0f;
    float m0 = -3.402823466e38f, m1 = -3.402823466e38f;
    float l0 = 0.0f, l1 = 0.0f;

    const float* bdp = bdbuf + (size_t)bn * BDSZ + 1024;

    for (int j0 = 0; j0 < KLEN; j0 += 128) {
        __syncthreads();
        // stage K and V tiles (128 x 64 each) as tf32
        #pragma unroll
        for (int it = 0; it < 16; it++) {
            int fi = tid + it * 128;
            int r = fi >> 4, c4 = (fi & 15) * 4;
            const float* base = kv + ((size_t)(j0 + r) * 2 + b) * (2 * NHD) + n * DH + c4;
            float4 kx = *(const float4*)base;
            *(uint4*)&Ks[r][c4] = make_uint4(f2tf(kx.x), f2tf(kx.y), f2tf(kx.z), f2tf(kx.w));
            float4 vx = *(const float4*)(base + NHD);
            *(uint4*)&Vs[r][c4] = make_uint4(f2tf(vx.x), f2tf(vx.y), f2tf(vx.z), f2tf(vx.w));
        }
        __syncthreads();

        // ---- S = Q . K^T ----
        float s[16][4];
        #pragma unroll
        for (int nt = 0; nt < 16; nt++)
            #pragma unroll
            for (int r = 0; r < 4; r++) s[nt][r] = 0.0f;

        #pragma unroll
        for (int g = 0; g < 8; g++) {
            #pragma unroll
            for (int nt = 0; nt < 16; nt++) {
                uint32_t bf[2];
                int j = nt * 8 + row;
                bf[0] = Ks[j][g * 8 + qd];
                bf[1] = Ks[j][g * 8 + 4 + qd];
                mma8(s[nt], qf[g], bf);
            }
        }

        // ---- add shifted BD (contiguous reads) + scale ----
        #pragma unroll
        for (int nt = 0; nt < 16; nt++) {
            int jc = j0 + nt * 8 + 2 * qd;
            float2 b0 = *(const float2*)(bdp + (size_t)ir0 * KLEN + jc);
            float2 b1 = *(const float2*)(bdp + (size_t)(ir0 + 8) * KLEN + jc);
            s[nt][0] = (s[nt][0] + b0.x) * 0.125f;
            s[nt][1] = (s[nt][1] + b0.y) * 0.125f;
            s[nt][2] = (s[nt][2] + b1.x) * 0.125f;
            s[nt][3] = (s[nt][3] + b1.y) * 0.125f;
        }

        // ---- online softmax update ----
        float tm0 = -3.402823466e38f, tm1 = -3.402823466e38f;
        #pragma unroll
        for (int nt = 0; nt < 16; nt++) {
            tm0 = fmaxf(tm0, fmaxf(s[nt][0], s[nt][1]));
            tm1 = fmaxf(tm1, fmaxf(s[nt][2], s[nt][3]));
        }
        tm0 = fmaxf(tm0, __shfl_xor_sync(0xffffffffu, tm0, 1));
        tm0 = fmaxf(tm0, __shfl_xor_sync(0xffffffffu, tm0, 2));
        tm1 = fmaxf(tm1, __shfl_xor_sync(0xffffffffu, tm1, 1));
        tm1 = fmaxf(tm1, __shfl_xor_sync(0xffffffffu, tm1, 2));

        float nm0 = fmaxf(m0, tm0), nm1 = fmaxf(m1, tm1);
        float sc0 = __expf(m0 - nm0), sc1 = __expf(m1 - nm1);
        m0 = nm0; m1 = nm1;

        float ps0 = 0.0f, ps1 = 0.0f;
        #pragma unroll
        for (int nt = 0; nt < 16; nt++) {
            s[nt][0] = __expf(s[nt][0] - m0);
            s[nt][1] = __expf(s[nt][1] - m0);
            s[nt][2] = __expf(s[nt][2] - m1);
            s[nt][3] = __expf(s[nt][3] - m1);
            ps0 += s[nt][0] + s[nt][1];
            ps1 += s[nt][2] + s[nt][3];
        }
        l0 = l0 * sc0 + ps0;
        l1 = l1 * sc1 + ps1;
        #pragma unroll
        for (int dt = 0; dt < 8; dt++) {
            Ov[dt][0] *= sc0; Ov[dt][1] *= sc0;
            Ov[dt][2] *= sc1; Ov[dt][3] *= sc1;
        }

        // ---- P (C-layout) -> A-frags via shuffle, then O += P.V ----
        const int srcA = (lane & 28) | (qd >> 1);
        const int srcB = srcA | 2;
        const bool odd = qd & 1;
        #pragma unroll
        for (int g = 0; g < 16; g++) {
            uint32_t p0 = f2tf(s[g][0]), p1 = f2tf(s[g][1]);
            uint32_t p2 = f2tf(s[g][2]), p3 = f2tf(s[g][3]);
            uint32_t t00 = __shfl_sync(0xffffffffu, p0, srcA);
            uint32_t t01 = __shfl_sync(0xffffffffu, p1, srcA);
            uint32_t t10 = __shfl_sync(0xffffffffu, p2, srcA);
            uint32_t t11 = __shfl_sync(0xffffffffu, p3, srcA);
            uint32_t u00 = __shfl_sync(0xffffffffu, p0, srcB);
            uint32_t u01 = __shfl_sync(0xffffffffu, p1, srcB);
            uint32_t u10 = __shfl_sync(0xffffffffu, p2, srcB);
            uint32_t u11 = __shfl_sync(0xffffffffu, p3, srcB);
            uint32_t a[4];
            a[0] = odd ? t01 : t00;
            a[1] = odd ? t11 : t10;
            a[2] = odd ? u01 : u00;
            a[3] = odd ? u11 : u10;
            #pragma unroll
            for (int dt = 0; dt < 8; dt++) {
                uint32_t bf[2];
                bf[0] = Vs[g * 8 + qd][dt * 8 + row];
                bf[1] = Vs[g * 8 + 4 + qd][dt * 8 + row];
                mma8(Ov[dt], a, bf);
            }
        }
    }

    // ---- finalize: normalize and write ----
    l0 += __shfl_xor_sync(0xffffffffu, l0, 1);
    l0 += __shfl_xor_sync(0xffffffffu, l0, 2);
    l1 += __shfl_xor_sync(0xffffffffu, l1, 1);
    l1 += __shfl_xor_sync(0xffffffffu, l1, 2);
    float inv0 = 1.0f / l0, inv1 = 1.0f / l1;

    #pragma unroll
    for (int dt = 0; dt < 8; dt++) {
        int d = n * DH + dt * 8 + 2 * qd;
        *(float2*)&av[(size_t)(ir0 * 2 + b) * NHD + d] =
            make_float2(Ov[dt][0] * inv0, Ov[dt][1] * inv0);
        *(float2*)&av[(size_t)((ir0 + 8) * 2 + b) * NHD + d] =
            make_float2(Ov[dt][2] * inv1, Ov[dt][3] * inv1);
    }
}

// ---------------------------------------------------------------------------
extern "C" void kernel_launch(void* const* d_in, const int* in_sizes, int n_in,
                              void* d_out, int out_size)
{
    const float* w   = (const float*)d_in[0];
    const float* r   = (const float*)d_in[1];
    const float* rwb = (const float*)d_in[2];
    const float* rrb = (const float*)d_in[3];
    const float* Wq  = (const float*)d_in[4];
    const float* Wkv = (const float*)d_in[5];
    const float* Wr  = (const float*)d_in[6];
    const float* Wo  = (const float*)d_in[7];
    float* out = (float*)d_out;

    float *qh, *kv, *rk, *bd, *av;
    cudaGetSymbolAddress((void**)&qh, g_qh);
    cudaGetSymbolAddress((void**)&kv, g_kv);
    cudaGetSymbolAddress((void**)&rk, g_rk);
    cudaGetSymbolAddress((void**)&bd, g_bd);
    cudaGetSymbolAddress((void**)&av, g_av);

    static int attr_set = 0;
    if (!attr_set) {
        cudaFuncSetAttribute(scores_bd_tf32,
                             cudaFuncAttributeMaxDynamicSharedMemorySize,
                             2 * 128 * 68 * 4);
        cudaFuncSetAttribute(attn_fused,
                             cudaFuncAttributeMaxDynamicSharedMemorySize,
                             (128 * 68 + 128 * 72) * 4);
        attr_set = 1;
    }
    const int score_smem = 2 * 128 * 68 * 4;
    const int fused_smem = (128 * 68 + 128 * 72) * 4;

    // projections
    gemm_tf32<<<dim3(1024 / 128, 2048 / 128), 256>>>(
        w + (size_t)QLEN * BSZ * DM, Wq, qh, 2048, 1024, 1024);
    gemm_tf32<<<dim3(2048 / 128, 4096 / 128), 256>>>(w, Wkv, kv, 4096, 2048, 1024);
    gemm_tf32<<<dim3(1024 / 128, 2048 / 128), 256>>>(r, Wr, rk, 2048, 1024, 1024);

    // shifted BD buffer: diag zeros + BD scores written in shifted layout
    zero_diag<<<32, 1024>>>(bd);
    scores_bd_tf32<<<dim3(RLEN / 128, QLEN / 128, 32), 256, score_smem>>>(
        qh, rk, rrb, bd);

    // fused attention (AC + BDshift + softmax + PV)
    attn_fused<<<dim3(QLEN / 64, BSZ * NH), 128, fused_smem>>>(
        qh, kv, bd, rwb, av);

    // output projection
    gemm_tf32<<<dim3(1024 / 128, 2048 / 128), 256>>>(av, Wo, out, 2048, 1024, 1024);
}

// round 4
// speedup vs baseline: 2.9251x; 1.0738x over previous
#include <cuda_runtime.h>
#include <math.h>
#include <stdint.h>

#define QLEN 1024
#define KLEN 2048
#define RLEN 2048
#define BSZ  2
#define DM   1024
#define NH   16
#define DH   64
#define NHD  1024   // NH*DH

#define BDSTRIDE 2049
#define BDSZ     2098176   // per-(b,n) shifted-BD buffer: 1023*2049+2048+1

// -------------------- scratch (device globals) ------------------------------
__device__ float g_qh[QLEN * BSZ * NHD];
__device__ float g_kv[KLEN * BSZ * 2 * NHD];
__device__ float g_rk[RLEN * NHD];
__device__ float g_bd[(size_t)BSZ * NH * BDSZ];
__device__ float g_av[QLEN * BSZ * NHD];

// -------------------- tf32 helpers ------------------------------------------
__device__ __forceinline__ uint32_t f2tf(float x) {
    uint32_t r;
    asm("cvt.rna.tf32.f32 %0, %1;" : "=r"(r) : "f"(x));
    return r;
}

__device__ __forceinline__ void mma8(float* d, const uint32_t* a, const uint32_t* b) {
    asm volatile(
        "mma.sync.aligned.m16n8k8.row.col.f32.tf32.tf32.f32 "
        "{%0,%1,%2,%3},{%4,%5,%6,%7},{%8,%9},{%0,%1,%2,%3};\n"
        : "+f"(d[0]), "+f"(d[1]), "+f"(d[2]), "+f"(d[3])
        : "r"(a[0]), "r"(a[1]), "r"(a[2]), "r"(a[3]), "r"(b[0]), "r"(b[1]));
}

// -------------------- generic tf32 GEMM: C[M,N] = A[M,K] @ B[K,N] -----------
__global__ __launch_bounds__(256) void gemm_tf32(
    const float* __restrict__ A, const float* __restrict__ B,
    float* __restrict__ C, int M, int N, int K)
{
    __shared__ uint32_t As[128][20];
    __shared__ uint32_t Bs[16][136];
    const int tid  = threadIdx.x;
    const int lane = tid & 31;
    const int warp = tid >> 5;
    const int wm = (warp >> 2) * 64;
    const int wn = (warp & 3) * 32;
    const int row0 = blockIdx.y * 128, col0 = blockIdx.x * 128;

    float acc[4][4][4];
    #pragma unroll
    for (int i = 0; i < 4; i++)
        #pragma unroll
        for (int j = 0; j < 4; j++)
            #pragma unroll
            for (int r = 0; r < 4; r++) acc[i][j][r] = 0.0f;

    const int am = tid >> 1, aks = (tid & 1) * 8;
    const int bk = tid >> 4, bns = (tid & 15) * 8;

    for (int k0 = 0; k0 < K; k0 += 16) {
        const float4* ap = (const float4*)(A + (size_t)(row0 + am) * K + k0 + aks);
        float4 a0 = ap[0], a1 = ap[1];
        *(uint4*)&As[am][aks]     = make_uint4(f2tf(a0.x), f2tf(a0.y), f2tf(a0.z), f2tf(a0.w));
        *(uint4*)&As[am][aks + 4] = make_uint4(f2tf(a1.x), f2tf(a1.y), f2tf(a1.z), f2tf(a1.w));
        const float4* bp = (const float4*)(B + (size_t)(k0 + bk) * N + col0 + bns);
        float4 b0 = bp[0], b1 = bp[1];
        *(uint4*)&Bs[bk][bns]     = make_uint4(f2tf(b0.x), f2tf(b0.y), f2tf(b0.z), f2tf(b0.w));
        *(uint4*)&Bs[bk][bns + 4] = make_uint4(f2tf(b1.x), f2tf(b1.y), f2tf(b1.z), f2tf(b1.w));
        __syncthreads();

        #pragma unroll
        for (int kk = 0; kk < 16; kk += 8) {
            uint32_t af[4][4];
            #pragma unroll
            for (int mt = 0; mt < 4; mt++) {
                int r = wm + mt * 16 + (lane >> 2);
                int c = kk + (lane & 3);
                af[mt][0] = As[r][c];
                af[mt][1] = As[r + 8][c];
                af[mt][2] = As[r][c + 4];
                af[mt][3] = As[r + 8][c + 4];
            }
            #pragma unroll
            for (int nt = 0; nt < 4; nt++) {
                uint32_t bf[2];
                int n = wn + nt * 8 + (lane >> 2);
                bf[0] = Bs[kk + (lane & 3)][n];
                bf[1] = Bs[kk + 4 + (lane & 3)][n];
                #pragma unroll
                for (int mt = 0; mt < 4; mt++) mma8(acc[mt][nt], af[mt], bf);
            }
        }
        __syncthreads();
    }

    #pragma unroll
    for (int mt = 0; mt < 4; mt++)
        #pragma unroll
        for (int nt = 0; nt < 4; nt++) {
            int r = row0 + wm + mt * 16 + (lane >> 2);
            int c = col0 + wn + nt * 8 + 2 * (lane & 3);
            *(float2*)&C[(size_t)r * N + c]       = make_float2(acc[mt][nt][0], acc[mt][nt][1]);
            *(float2*)&C[(size_t)(r + 8) * N + c] = make_float2(acc[mt][nt][2], acc[mt][nt][3]);
        }
}

// -------------------- BD scores (tf32) -> shifted layout --------------------
extern __shared__ uint32_t s_dyn[];
__global__ __launch_bounds__(256) void scores_bd_tf32(
    const float* __restrict__ qh, const float* __restrict__ rk,
    const float* __restrict__ bias, float* __restrict__ out)
{
    uint32_t (*Qs)[68] = (uint32_t(*)[68])s_dyn;
    uint32_t (*Ks)[68] = (uint32_t(*)[68])(s_dyn + 128 * 68);

    const int bn = blockIdx.z;
    const int b = bn >> 4, n = bn & 15;
    const int j0 = blockIdx.x * 128, i0 = blockIdx.y * 128;
    const int tid  = threadIdx.x;
    const int lane = tid & 31;
    const int warp = tid >> 5;
    const int wm = (warp >> 2) * 64;
    const int wn = (warp & 3) * 32;

    const int m = tid >> 1, half = (tid & 1) * 32;
    const float* qrow = qh + (size_t)((i0 + m) * 2 + b) * NHD + n * DH + half;
    const float* krow = rk + (size_t)(j0 + m) * NHD + n * DH + half;
    const float4* bias4 = (const float4*)(bias + n * DH + half);

    #pragma unroll
    for (int q = 0; q < 8; q++) {
        float4 qv = ((const float4*)qrow)[q];
        float4 bv = bias4[q];
        int d = half + q * 4;
        *(uint4*)&Qs[m][d] = make_uint4(f2tf(qv.x + bv.x), f2tf(qv.y + bv.y),
                                        f2tf(qv.z + bv.z), f2tf(qv.w + bv.w));
        float4 kv4 = ((const float4*)krow)[q];
        *(uint4*)&Ks[m][d] = make_uint4(f2tf(kv4.x), f2tf(kv4.y), f2tf(kv4.z), f2tf(kv4.w));
    }
    __syncthreads();

    float acc[4][4][4];
    #pragma unroll
    for (int i = 0; i < 4; i++)
        #pragma unroll
        for (int j = 0; j < 4; j++)
            #pragma unroll
            for (int r = 0; r < 4; r++) acc[i][j][r] = 0.0f;

    #pragma unroll
    for (int kk = 0; kk < 64; kk += 8) {
        uint32_t af[4][4];
        #pragma unroll
        for (int mt = 0; mt < 4; mt++) {
            int r = wm + mt * 16 + (lane >> 2);
            int c = kk + (lane & 3);
            af[mt][0] = Qs[r][c];
            af[mt][1] = Qs[r + 8][c];
            af[mt][2] = Qs[r][c + 4];
            af[mt][3] = Qs[r + 8][c + 4];
        }
        #pragma unroll
        for (int nt = 0; nt < 4; nt++) {
            uint32_t bf[2];
            int j = wn + nt * 8 + (lane >> 2);
            bf[0] = Ks[j][kk + (lane & 3)];
            bf[1] = Ks[j][kk + 4 + (lane & 3)];
            #pragma unroll
            for (int mt = 0; mt < 4; mt++) mma8(acc[mt][nt], af[mt], bf);
        }
    }

    float* ob = out + (size_t)bn * BDSZ;
    #pragma unroll
    for (int mt = 0; mt < 4; mt++)
        #pragma unroll
        for (int nt = 0; nt < 4; nt++) {
            int r = i0 + wm + mt * 16 + (lane >> 2);
            int c = j0 + wn + nt * 8 + 2 * (lane & 3);
            size_t p0 = (size_t)r * BDSTRIDE + c + 1;
            size_t p1 = (size_t)(r + 8) * BDSTRIDE + c + 1;
            ob[p0]     = acc[mt][nt][0];
            ob[p0 + 1] = acc[mt][nt][1];
            ob[p1]     = acc[mt][nt][2];
            ob[p1 + 1] = acc[mt][nt][3];
        }
}

// zero the "dropped column" positions of the shifted buffer
__global__ void zero_diag(float* __restrict__ buf) {
    int k = blockIdx.x * blockDim.x + threadIdx.x;
    int bn = k >> 10, kk = k & 1023;
    if (kk >= 1)
        buf[(size_t)bn * BDSZ + (size_t)kk * BDSTRIDE] = 0.0f;
}

// -------------------- fused attention v2 ------------------------------------
// grid (QLEN/128, 32), 128 threads = 4 warps, warp = 32 q-rows (mt=2).
// Softmax per 64-col chunk; B-fragment LDS amortized over mt=2 (1.0 LDS/MMA).
__global__ __launch_bounds__(128, 2) void attn_fused(
    const float* __restrict__ qh, const float* __restrict__ kv,
    const float* __restrict__ bdbuf, const float* __restrict__ rwb,
    float* __restrict__ av)
{
    extern __shared__ uint32_t smem[];
    uint32_t (*Ks)[68] = (uint32_t(*)[68])smem;              // [j][d]
    uint32_t (*Vs)[72] = (uint32_t(*)[72])(smem + 128 * 68); // [j][d]

    const int bn = blockIdx.y;
    const int b = bn >> 4, n = bn & 15;
    const int i0 = blockIdx.x * 128;
    const int tid  = threadIdx.x;
    const int lane = tid & 31;
    const int warp = tid >> 5;
    const int row = lane >> 2;   // 0..7
    const int qd  = lane & 3;    // 0..3
    int irow[2];
    irow[0] = i0 + warp * 32 + row;
    irow[1] = irow[0] + 16;

    // ---- Q fragments with r_w_bias folded in ----
    uint32_t qf[2][8][4];
    #pragma unroll
    for (int mt = 0; mt < 2; mt++) {
        const float* q0 = qh + (size_t)(irow[mt] * 2 + b) * NHD + n * DH;
        const float* q1 = q0 + 16 * NHD;   // row +8
        const float* bias = rwb + n * DH;
        #pragma unroll
        for (int g = 0; g < 8; g++) {
            int d0 = g * 8 + qd, d1 = d0 + 4;
            qf[mt][g][0] = f2tf(q0[d0] + bias[d0]);
            qf[mt][g][1] = f2tf(q1[d0] + bias[d0]);
            qf[mt][g][2] = f2tf(q0[d1] + bias[d1]);
            qf[mt][g][3] = f2tf(q1[d1] + bias[d1]);
        }
    }

    float Ov[2][8][4];
    #pragma unroll
    for (int mt = 0; mt < 2; mt++)
        #pragma unroll
        for (int dt = 0; dt < 8; dt++)
            #pragma unroll
            for (int r = 0; r < 4; r++) Ov[mt][dt][r] = 0.0f;
    float mrow[2][2] = {{-3.402823466e38f, -3.402823466e38f},
                        {-3.402823466e38f, -3.402823466e38f}};
    float lrow[2][2] = {{0.0f, 0.0f}, {0.0f, 0.0f}};

    const float* bdp = bdbuf + (size_t)bn * BDSZ + 1024;

    const int srcA = (lane & 28) | (qd >> 1);
    const int srcB = srcA | 2;
    const bool odd = qd & 1;

    for (int j0 = 0; j0 < KLEN; j0 += 128) {
        __syncthreads();
        #pragma unroll
        for (int it = 0; it < 16; it++) {
            int fi = tid + it * 128;
            int r = fi >> 4, c4 = (fi & 15) * 4;
            const float* base = kv + ((size_t)(j0 + r) * 2 + b) * (2 * NHD) + n * DH + c4;
            float4 kx = *(const float4*)base;
            *(uint4*)&Ks[r][c4] = make_uint4(f2tf(kx.x), f2tf(kx.y), f2tf(kx.z), f2tf(kx.w));
            float4 vx = *(const float4*)(base + NHD);
            *(uint4*)&Vs[r][c4] = make_uint4(f2tf(vx.x), f2tf(vx.y), f2tf(vx.z), f2tf(vx.w));
        }
        __syncthreads();

        #pragma unroll
        for (int ch = 0; ch < 2; ch++) {
            const int jl = ch * 64;

            // ---- S = Q . K^T over 64-col chunk ----
            float s[2][8][4];
            #pragma unroll
            for (int mt = 0; mt < 2; mt++)
                #pragma unroll
                for (int nt = 0; nt < 8; nt++)
                    #pragma unroll
                    for (int r = 0; r < 4; r++) s[mt][nt][r] = 0.0f;

            #pragma unroll
            for (int g = 0; g < 8; g++) {
                #pragma unroll
                for (int nt = 0; nt < 8; nt++) {
                    uint32_t bf[2];
                    int j = jl + nt * 8 + row;
                    bf[0] = Ks[j][g * 8 + qd];
                    bf[1] = Ks[j][g * 8 + 4 + qd];
                    mma8(s[0][nt], qf[0][g], bf);
                    mma8(s[1][nt], qf[1][g], bf);
                }
            }

            // ---- add shifted BD + scale ----
            #pragma unroll
            for (int mt = 0; mt < 2; mt++) {
                #pragma unroll
                for (int nt = 0; nt < 8; nt++) {
                    int jc = j0 + jl + nt * 8 + 2 * qd;
                    float2 b0 = *(const float2*)(bdp + (size_t)irow[mt] * KLEN + jc);
                    float2 b1 = *(const float2*)(bdp + (size_t)(irow[mt] + 8) * KLEN + jc);
                    s[mt][nt][0] = (s[mt][nt][0] + b0.x) * 0.125f;
                    s[mt][nt][1] = (s[mt][nt][1] + b0.y) * 0.125f;
                    s[mt][nt][2] = (s[mt][nt][2] + b1.x) * 0.125f;
                    s[mt][nt][3] = (s[mt][nt][3] + b1.y) * 0.125f;
                }
            }

            // ---- online softmax (per mt, per row-half) ----
            #pragma unroll
            for (int mt = 0; mt < 2; mt++) {
                float tm0 = -3.402823466e38f, tm1 = -3.402823466e38f;
                #pragma unroll
                for (int nt = 0; nt < 8; nt++) {
                    tm0 = fmaxf(tm0, fmaxf(s[mt][nt][0], s[mt][nt][1]));
                    tm1 = fmaxf(tm1, fmaxf(s[mt][nt][2], s[mt][nt][3]));
                }
                tm0 = fmaxf(tm0, __shfl_xor_sync(0xffffffffu, tm0, 1));
                tm0 = fmaxf(tm0, __shfl_xor_sync(0xffffffffu, tm0, 2));
                tm1 = fmaxf(tm1, __shfl_xor_sync(0xffffffffu, tm1, 1));
                tm1 = fmaxf(tm1, __shfl_xor_sync(0xffffffffu, tm1, 2));

                float nm0 = fmaxf(mrow[mt][0], tm0), nm1 = fmaxf(mrow[mt][1], tm1);
                float sc0 = __expf(mrow[mt][0] - nm0), sc1 = __expf(mrow[mt][1] - nm1);
                mrow[mt][0] = nm0; mrow[mt][1] = nm1;

                float ps0 = 0.0f, ps1 = 0.0f;
                #pragma unroll
                for (int nt = 0; nt < 8; nt++) {
                    s[mt][nt][0] = __expf(s[mt][nt][0] - nm0);
                    s[mt][nt][1] = __expf(s[mt][nt][1] - nm0);
                    s[mt][nt][2] = __expf(s[mt][nt][2] - nm1);
                    s[mt][nt][3] = __expf(s[mt][nt][3] - nm1);
                    ps0 += s[mt][nt][0] + s[mt][nt][1];
                    ps1 += s[mt][nt][2] + s[mt][nt][3];
                }
                lrow[mt][0] = lrow[mt][0] * sc0 + ps0;
                lrow[mt][1] = lrow[mt][1] * sc1 + ps1;
                #pragma unroll
                for (int dt = 0; dt < 8; dt++) {
                    Ov[mt][dt][0] *= sc0; Ov[mt][dt][1] *= sc0;
                    Ov[mt][dt][2] *= sc1; Ov[mt][dt][3] *= sc1;
                }
            }

            // ---- P -> A-frags via shuffle, O += P.V ----
            #pragma unroll
            for (int g = 0; g < 8; g++) {
                uint32_t a[2][4];
                #pragma unroll
                for (int mt = 0; mt < 2; mt++) {
                    uint32_t p0 = f2tf(s[mt][g][0]), p1 = f2tf(s[mt][g][1]);
                    uint32_t p2 = f2tf(s[mt][g][2]), p3 = f2tf(s[mt][g][3]);
                    uint32_t t00 = __shfl_sync(0xffffffffu, p0, srcA);
                    uint32_t t01 = __shfl_sync(0xffffffffu, p1, srcA);
                    uint32_t t10 = __shfl_sync(0xffffffffu, p2, srcA);
                    uint32_t t11 = __shfl_sync(0xffffffffu, p3, srcA);
                    uint32_t u00 = __shfl_sync(0xffffffffu, p0, srcB);
                    uint32_t u01 = __shfl_sync(0xffffffffu, p1, srcB);
                    uint32_t u10 = __shfl_sync(0xffffffffu, p2, srcB);
                    uint32_t u11 = __shfl_sync(0xffffffffu, p3, srcB);
                    a[mt][0] = odd ? t01 : t00;
                    a[mt][1] = odd ? t11 : t10;
                    a[mt][2] = odd ? u01 : u00;
                    a[mt][3] = odd ? u11 : u10;
                }
                #pragma unroll
                for (int dt = 0; dt < 8; dt++) {
                    uint32_t bf[2];
                    bf[0] = Vs[jl + g * 8 + qd][dt * 8 + row];
                    bf[1] = Vs[jl + g * 8 + 4 + qd][dt * 8 + row];
                    mma8(Ov[0][dt], a[0], bf);
                    mma8(Ov[1][dt], a[1], bf);
                }
            }
        }
    }

    // ---- finalize ----
    #pragma unroll
    for (int mt = 0; mt < 2; mt++) {
        float l0 = lrow[mt][0], l1 = lrow[mt][1];
        l0 += __shfl_xor_sync(0xffffffffu, l0, 1);
        l0 += __shfl_xor_sync(0xffffffffu, l0, 2);
        l1 += __shfl_xor_sync(0xffffffffu, l1, 1);
        l1 += __shfl_xor_sync(0xffffffffu, l1, 2);
        float inv0 = 1.0f / l0, inv1 = 1.0f / l1;
        #pragma unroll
        for (int dt = 0; dt < 8; dt++) {
            int d = n * DH + dt * 8 + 2 * qd;
            *(float2*)&av[(size_t)(irow[mt] * 2 + b) * NHD + d] =
                make_float2(Ov[mt][dt][0] * inv0, Ov[mt][dt][1] * inv0);
            *(float2*)&av[(size_t)((irow[mt] + 8) * 2 + b) * NHD + d] =
                make_float2(Ov[mt][dt][2] * inv1, Ov[mt][dt][3] * inv1);
        }
    }
}

// ---------------------------------------------------------------------------
extern "C" void kernel_launch(void* const* d_in, const int* in_sizes, int n_in,
                              void* d_out, int out_size)
{
    const float* w   = (const float*)d_in[0];
    const float* r   = (const float*)d_in[1];
    const float* rwb = (const float*)d_in[2];
    const float* rrb = (const float*)d_in[3];
    const float* Wq  = (const float*)d_in[4];
    const float* Wkv = (const float*)d_in[5];
    const float* Wr  = (const float*)d_in[6];
    const float* Wo  = (const float*)d_in[7];
    float* out = (float*)d_out;

    float *qh, *kv, *rk, *bd, *av;
    cudaGetSymbolAddress((void**)&qh, g_qh);
    cudaGetSymbolAddress((void**)&kv, g_kv);
    cudaGetSymbolAddress((void**)&rk, g_rk);
    cudaGetSymbolAddress((void**)&bd, g_bd);
    cudaGetSymbolAddress((void**)&av, g_av);

    static cudaStream_t st1 = 0, st2 = 0;
    static cudaEvent_t ev0 = 0, evKV = 0, evR = 0;
    if (!st1) {
        cudaStreamCreateWithFlags(&st1, cudaStreamNonBlocking);
        cudaStreamCreateWithFlags(&st2, cudaStreamNonBlocking);
        cudaEventCreateWithFlags(&ev0,  cudaEventDisableTiming);
        cudaEventCreateWithFlags(&evKV, cudaEventDisableTiming);
        cudaEventCreateWithFlags(&evR,  cudaEventDisableTiming);
        cudaFuncSetAttribute(scores_bd_tf32,
                             cudaFuncAttributeMaxDynamicSharedMemorySize,
                             2 * 128 * 68 * 4);
        cudaFuncSetAttribute(attn_fused,
                             cudaFuncAttributeMaxDynamicSharedMemorySize,
                             (128 * 68 + 128 * 72) * 4);
    }
    const int score_smem = 2 * 128 * 68 * 4;
    const int fused_smem = (128 * 68 + 128 * 72) * 4;

    // fork side streams off the captured stream
    cudaEventRecord(ev0, 0);
    cudaStreamWaitEvent(st1, ev0, 0);
    cudaStreamWaitEvent(st2, ev0, 0);

    // stream 0: Wq projection
    gemm_tf32<<<dim3(1024 / 128, 2048 / 128), 256, 0, 0>>>(
        w + (size_t)QLEN * BSZ * DM, Wq, qh, 2048, 1024, 1024);

    // st1: Wkv projection (largest, overlapped)
    gemm_tf32<<<dim3(2048 / 128, 4096 / 128), 256, 0, st1>>>(
        w, Wkv, kv, 4096, 2048, 1024);
    cudaEventRecord(evKV, st1);

    // st2: zero diag + Wr projection
    zero_diag<<<32, 1024, 0, st2>>>(bd);
    gemm_tf32<<<dim3(1024 / 128, 2048 / 128), 256, 0, st2>>>(
        r, Wr, rk, 2048, 1024, 1024);
    cudaEventRecord(evR, st2);

    // stream 0: BD scores (needs qh from stream0, rk+zeros from st2)
    cudaStreamWaitEvent(0, evR, 0);
    scores_bd_tf32<<<dim3(RLEN / 128, QLEN / 128, 32), 256, score_smem, 0>>>(
        qh, rk, rrb, bd);

    // stream 0: fused attention (needs kv from st1)
    cudaStreamWaitEvent(0, evKV, 0);
    attn_fused<<<dim3(QLEN / 128, BSZ * NH), 128, fused_smem, 0>>>(
        qh, kv, bd, rwb, av);

    // output projection
    gemm_tf32<<<dim3(1024 / 128, 2048 / 128), 256, 0, 0>>>(
        av, Wo, out, 2048, 1024, 1024);
}

// round 5
// speedup vs baseline: 3.0163x; 1.0312x over previous
#include <cuda_runtime.h>
#include <math.h>
#include <stdint.h>

#define QLEN 1024
#define KLEN 2048
#define RLEN 2048
#define BSZ  2
#define DM   1024
#define NH   16
#define DH   64
#define NHD  1024   // NH*DH

#define BDSTRIDE 2049
#define BDSZ     2098176   // per-(b,n) shifted-BD buffer: 1023*2049+2048+1

// -------------------- scratch (device globals) ------------------------------
__device__ float g_qh[QLEN * BSZ * NHD];
__device__ float g_kv[KLEN * BSZ * 2 * NHD];
__device__ float g_rk[RLEN * NHD];
__device__ float g_bd[(size_t)BSZ * NH * BDSZ];
__device__ float g_av[QLEN * BSZ * NHD];

// -------------------- tf32 helpers ------------------------------------------
__device__ __forceinline__ uint32_t f2tf(float x) {
    uint32_t r;
    asm("cvt.rna.tf32.f32 %0, %1;" : "=r"(r) : "f"(x));
    return r;
}

__device__ __forceinline__ void mma8(float* d, const uint32_t* a, const uint32_t* b) {
    asm volatile(
        "mma.sync.aligned.m16n8k8.row.col.f32.tf32.tf32.f32 "
        "{%0,%1,%2,%3},{%4,%5,%6,%7},{%8,%9},{%0,%1,%2,%3};\n"
        : "+f"(d[0]), "+f"(d[1]), "+f"(d[2]), "+f"(d[3])
        : "r"(a[0]), "r"(a[1]), "r"(a[2]), "r"(a[3]), "r"(b[0]), "r"(b[1]));
}

// -------------------- pipelined tf32 GEMM: C[M,N] = A[M,K] @ B[K,N] ---------
// 128x128 tile, BK=16, 256 thr, 8 warps (2x4), warp tile 64x32.
// Register-prefetch + SMEM ping-pong double buffering, one barrier per step.
__global__ __launch_bounds__(256) void gemm_tf32(
    const float* __restrict__ A, const float* __restrict__ B,
    float* __restrict__ C, int M, int N, int K)
{
    __shared__ uint32_t As[2][128][20];
    __shared__ uint32_t Bs[2][16][136];
    const int tid  = threadIdx.x;
    const int lane = tid & 31;
    const int warp = tid >> 5;
    const int wm = (warp >> 2) * 64;
    const int wn = (warp & 3) * 32;
    const int row0 = blockIdx.y * 128, col0 = blockIdx.x * 128;

    float acc[4][4][4];
    #pragma unroll
    for (int i = 0; i < 4; i++)
        #pragma unroll
        for (int j = 0; j < 4; j++)
            #pragma unroll
            for (int r = 0; r < 4; r++) acc[i][j][r] = 0.0f;

    const int am = tid >> 1, aks = (tid & 1) * 8;
    const int bk = tid >> 4, bns = (tid & 15) * 8;
    const float* aptr = A + (size_t)(row0 + am) * K + aks;
    const float* bptr = B + (size_t)bk * N + col0 + bns;

    float4 pa0, pa1, pb0, pb1;

    // prologue: load tile 0, stage into buffer 0
    pa0 = *(const float4*)(aptr);
    pa1 = *(const float4*)(aptr + 4);
    pb0 = *(const float4*)(bptr);
    pb1 = *(const float4*)(bptr + 4);
    *(uint4*)&As[0][am][aks]     = make_uint4(f2tf(pa0.x), f2tf(pa0.y), f2tf(pa0.z), f2tf(pa0.w));
    *(uint4*)&As[0][am][aks + 4] = make_uint4(f2tf(pa1.x), f2tf(pa1.y), f2tf(pa1.z), f2tf(pa1.w));
    *(uint4*)&Bs[0][bk][bns]     = make_uint4(f2tf(pb0.x), f2tf(pb0.y), f2tf(pb0.z), f2tf(pb0.w));
    *(uint4*)&Bs[0][bk][bns + 4] = make_uint4(f2tf(pb1.x), f2tf(pb1.y), f2tf(pb1.z), f2tf(pb1.w));
    __syncthreads();

    int buf = 0;
    for (int k0 = 0; k0 < K; k0 += 16) {
        const bool more = (k0 + 16) < K;
        if (more) {
            // prefetch next tile into registers (latency hidden under MMAs)
            pa0 = *(const float4*)(aptr + k0 + 16);
            pa1 = *(const float4*)(aptr + k0 + 20);
            pb0 = *(const float4*)(bptr + (size_t)(k0 + 16) * N);
            pb1 = *(const float4*)(bptr + (size_t)(k0 + 16) * N + 4);
        }

        #pragma unroll
        for (int kk = 0; kk < 16; kk += 8) {
            uint32_t af[4][4];
            #pragma unroll
            for (int mt = 0; mt < 4; mt++) {
                int r = wm + mt * 16 + (lane >> 2);
                int c = kk + (lane & 3);
                af[mt][0] = As[buf][r][c];
                af[mt][1] = As[buf][r + 8][c];
                af[mt][2] = As[buf][r][c + 4];
                af[mt][3] = As[buf][r + 8][c + 4];
            }
            #pragma unroll
            for (int nt = 0; nt < 4; nt++) {
                uint32_t bf[2];
                int n = wn + nt * 8 + (lane >> 2);
                bf[0] = Bs[buf][kk + (lane & 3)][n];
                bf[1] = Bs[buf][kk + 4 + (lane & 3)][n];
                #pragma unroll
                for (int mt = 0; mt < 4; mt++) mma8(acc[mt][nt], af[mt], bf);
            }
        }

        if (more) {
            int nb = buf ^ 1;
            *(uint4*)&As[nb][am][aks]     = make_uint4(f2tf(pa0.x), f2tf(pa0.y), f2tf(pa0.z), f2tf(pa0.w));
            *(uint4*)&As[nb][am][aks + 4] = make_uint4(f2tf(pa1.x), f2tf(pa1.y), f2tf(pa1.z), f2tf(pa1.w));
            *(uint4*)&Bs[nb][bk][bns]     = make_uint4(f2tf(pb0.x), f2tf(pb0.y), f2tf(pb0.z), f2tf(pb0.w));
            *(uint4*)&Bs[nb][bk][bns + 4] = make_uint4(f2tf(pb1.x), f2tf(pb1.y), f2tf(pb1.z), f2tf(pb1.w));
        }
        __syncthreads();
        buf ^= 1;
    }

    #pragma unroll
    for (int mt = 0; mt < 4; mt++)
        #pragma unroll
        for (int nt = 0; nt < 4; nt++) {
            int r = row0 + wm + mt * 16 + (lane >> 2);
            int c = col0 + wn + nt * 8 + 2 * (lane & 3);
            *(float2*)&C[(size_t)r * N + c]       = make_float2(acc[mt][nt][0], acc[mt][nt][1]);
            *(float2*)&C[(size_t)(r + 8) * N + c] = make_float2(acc[mt][nt][2], acc[mt][nt][3]);
        }
}

// -------------------- BD scores (tf32) -> shifted layout --------------------
extern __shared__ uint32_t s_dyn[];
__global__ __launch_bounds__(256) void scores_bd_tf32(
    const float* __restrict__ qh, const float* __restrict__ rk,
    const float* __restrict__ bias, float* __restrict__ out)
{
    uint32_t (*Qs)[68] = (uint32_t(*)[68])s_dyn;
    uint32_t (*Ks)[68] = (uint32_t(*)[68])(s_dyn + 128 * 68);

    const int bn = blockIdx.z;
    const int b = bn >> 4, n = bn & 15;
    const int j0 = blockIdx.x * 128, i0 = blockIdx.y * 128;
    const int tid  = threadIdx.x;
    const int lane = tid & 31;
    const int warp = tid >> 5;
    const int wm = (warp >> 2) * 64;
    const int wn = (warp & 3) * 32;

    const int m = tid >> 1, half = (tid & 1) * 32;
    const float* qrow = qh + (size_t)((i0 + m) * 2 + b) * NHD + n * DH + half;
    const float* krow = rk + (size_t)(j0 + m) * NHD + n * DH + half;
    const float4* bias4 = (const float4*)(bias + n * DH + half);

    #pragma unroll
    for (int q = 0; q < 8; q++) {
        float4 qv = ((const float4*)qrow)[q];
        float4 bv = bias4[q];
        int d = half + q * 4;
        *(uint4*)&Qs[m][d] = make_uint4(f2tf(qv.x + bv.x), f2tf(qv.y + bv.y),
                                        f2tf(qv.z + bv.z), f2tf(qv.w + bv.w));
        float4 kv4 = ((const float4*)krow)[q];
        *(uint4*)&Ks[m][d] = make_uint4(f2tf(kv4.x), f2tf(kv4.y), f2tf(kv4.z), f2tf(kv4.w));
    }
    __syncthreads();

    float acc[4][4][4];
    #pragma unroll
    for (int i = 0; i < 4; i++)
        #pragma unroll
        for (int j = 0; j < 4; j++)
            #pragma unroll
            for (int r = 0; r < 4; r++) acc[i][j][r] = 0.0f;

    #pragma unroll
    for (int kk = 0; kk < 64; kk += 8) {
        uint32_t af[4][4];
        #pragma unroll
        for (int mt = 0; mt < 4; mt++) {
            int r = wm + mt * 16 + (lane >> 2);
            int c = kk + (lane & 3);
            af[mt][0] = Qs[r][c];
            af[mt][1] = Qs[r + 8][c];
            af[mt][2] = Qs[r][c + 4];
            af[mt][3] = Qs[r + 8][c + 4];
        }
        #pragma unroll
        for (int nt = 0; nt < 4; nt++) {
            uint32_t bf[2];
            int j = wn + nt * 8 + (lane >> 2);
            bf[0] = Ks[j][kk + (lane & 3)];
            bf[1] = Ks[j][kk + 4 + (lane & 3)];
            #pragma unroll
            for (int mt = 0; mt < 4; mt++) mma8(acc[mt][nt], af[mt], bf);
        }
    }

    float* ob = out + (size_t)bn * BDSZ;
    #pragma unroll
    for (int mt = 0; mt < 4; mt++)
        #pragma unroll
        for (int nt = 0; nt < 4; nt++) {
            int r = i0 + wm + mt * 16 + (lane >> 2);
            int c = j0 + wn + nt * 8 + 2 * (lane & 3);
            size_t p0 = (size_t)r * BDSTRIDE + c + 1;
            size_t p1 = (size_t)(r + 8) * BDSTRIDE + c + 1;
            ob[p0]     = acc[mt][nt][0];
            ob[p0 + 1] = acc[mt][nt][1];
            ob[p1]     = acc[mt][nt][2];
            ob[p1 + 1] = acc[mt][nt][3];
        }
}

// zero the "dropped column" positions of the shifted buffer
__global__ void zero_diag(float* __restrict__ buf) {
    int k = blockIdx.x * blockDim.x + threadIdx.x;
    int bn = k >> 10, kk = k & 1023;
    if (kk >= 1)
        buf[(size_t)bn * BDSZ + (size_t)kk * BDSTRIDE] = 0.0f;
}

// -------------------- fused attention v2 ------------------------------------
__global__ __launch_bounds__(128, 2) void attn_fused(
    const float* __restrict__ qh, const float* __restrict__ kv,
    const float* __restrict__ bdbuf, const float* __restrict__ rwb,
    float* __restrict__ av)
{
    extern __shared__ uint32_t smem[];
    uint32_t (*Ks)[68] = (uint32_t(*)[68])smem;
    uint32_t (*Vs)[72] = (uint32_t(*)[72])(smem + 128 * 68);

    const int bn = blockIdx.y;
    const int b = bn >> 4, n = bn & 15;
    const int i0 = blockIdx.x * 128;
    const int tid  = threadIdx.x;
    const int lane = tid & 31;
    const int warp = tid >> 5;
    const int row = lane >> 2;
    const int qd  = lane & 3;
    int irow[2];
    irow[0] = i0 + warp * 32 + row;
    irow[1] = irow[0] + 16;

    uint32_t qf[2][8][4];
    #pragma unroll
    for (int mt = 0; mt < 2; mt++) {
        const float* q0 = qh + (size_t)(irow[mt] * 2 + b) * NHD + n * DH;
        const float* q1 = q0 + 16 * NHD;
        const float* bias = rwb + n * DH;
        #pragma unroll
        for (int g = 0; g < 8; g++) {
            int d0 = g * 8 + qd, d1 = d0 + 4;
            qf[mt][g][0] = f2tf(q0[d0] + bias[d0]);
            qf[mt][g][1] = f2tf(q1[d0] + bias[d0]);
            qf[mt][g][2] = f2tf(q0[d1] + bias[d1]);
            qf[mt][g][3] = f2tf(q1[d1] + bias[d1]);
        }
    }

    float Ov[2][8][4];
    #pragma unroll
    for (int mt = 0; mt < 2; mt++)
        #pragma unroll
        for (int dt = 0; dt < 8; dt++)
            #pragma unroll
            for (int r = 0; r < 4; r++) Ov[mt][dt][r] = 0.0f;
    float mrow[2][2] = {{-3.402823466e38f, -3.402823466e38f},
                        {-3.402823466e38f, -3.402823466e38f}};
    float lrow[2][2] = {{0.0f, 0.0f}, {0.0f, 0.0f}};

    const float* bdp = bdbuf + (size_t)bn * BDSZ + 1024;

    const int srcA = (lane & 28) | (qd >> 1);
    const int srcB = srcA | 2;
    const bool odd = qd & 1;

    for (int j0 = 0; j0 < KLEN; j0 += 128) {
        __syncthreads();
        #pragma unroll
        for (int it = 0; it < 16; it++) {
            int fi = tid + it * 128;
            int r = fi >> 4, c4 = (fi & 15) * 4;
            const float* base = kv + ((size_t)(j0 + r) * 2 + b) * (2 * NHD) + n * DH + c4;
            float4 kx = *(const float4*)base;
            *(uint4*)&Ks[r][c4] = make_uint4(f2tf(kx.x), f2tf(kx.y), f2tf(kx.z), f2tf(kx.w));
            float4 vx = *(const float4*)(base + NHD);
            *(uint4*)&Vs[r][c4] = make_uint4(f2tf(vx.x), f2tf(vx.y), f2tf(vx.z), f2tf(vx.w));
        }
        __syncthreads();

        #pragma unroll
        for (int ch = 0; ch < 2; ch++) {
            const int jl = ch * 64;

            float s[2][8][4];
            #pragma unroll
            for (int mt = 0; mt < 2; mt++)
                #pragma unroll
                for (int nt = 0; nt < 8; nt++)
                    #pragma unroll
                    for (int r = 0; r < 4; r++) s[mt][nt][r] = 0.0f;

            #pragma unroll
            for (int g = 0; g < 8; g++) {
                #pragma unroll
                for (int nt = 0; nt < 8; nt++) {
                    uint32_t bf[2];
                    int j = jl + nt * 8 + row;
                    bf[0] = Ks[j][g * 8 + qd];
                    bf[1] = Ks[j][g * 8 + 4 + qd];
                    mma8(s[0][nt], qf[0][g], bf);
                    mma8(s[1][nt], qf[1][g], bf);
                }
            }

            #pragma unroll
            for (int mt = 0; mt < 2; mt++) {
                #pragma unroll
                for (int nt = 0; nt < 8; nt++) {
                    int jc = j0 + jl + nt * 8 + 2 * qd;
                    float2 b0 = *(const float2*)(bdp + (size_t)irow[mt] * KLEN + jc);
                    float2 b1 = *(const float2*)(bdp + (size_t)(irow[mt] + 8) * KLEN + jc);
                    s[mt][nt][0] = (s[mt][nt][0] + b0.x) * 0.125f;
                    s[mt][nt][1] = (s[mt][nt][1] + b0.y) * 0.125f;
                    s[mt][nt][2] = (s[mt][nt][2] + b1.x) * 0.125f;
                    s[mt][nt][3] = (s[mt][nt][3] + b1.y) * 0.125f;
                }
            }

            #pragma unroll
            for (int mt = 0; mt < 2; mt++) {
                float tm0 = -3.402823466e38f, tm1 = -3.402823466e38f;
                #pragma unroll
                for (int nt = 0; nt < 8; nt++) {
                    tm0 = fmaxf(tm0, fmaxf(s[mt][nt][0], s[mt][nt][1]));
                    tm1 = fmaxf(tm1, fmaxf(s[mt][nt][2], s[mt][nt][3]));
                }
                tm0 = fmaxf(tm0, __shfl_xor_sync(0xffffffffu, tm0, 1));
                tm0 = fmaxf(tm0, __shfl_xor_sync(0xffffffffu, tm0, 2));
                tm1 = fmaxf(tm1, __shfl_xor_sync(0xffffffffu, tm1, 1));
                tm1 = fmaxf(tm1, __shfl_xor_sync(0xffffffffu, tm1, 2));

                float nm0 = fmaxf(mrow[mt][0], tm0), nm1 = fmaxf(mrow[mt][1], tm1);
                float sc0 = __expf(mrow[mt][0] - nm0), sc1 = __expf(mrow[mt][1] - nm1);
                mrow[mt][0] = nm0; mrow[mt][1] = nm1;

                float ps0 = 0.0f, ps1 = 0.0f;
                #pragma unroll
                for (int nt = 0; nt < 8; nt++) {
                    s[mt][nt][0] = __expf(s[mt][nt][0] - nm0);
                    s[mt][nt][1] = __expf(s[mt][nt][1] - nm0);
                    s[mt][nt][2] = __expf(s[mt][nt][2] - nm1);
                    s[mt][nt][3] = __expf(s[mt][nt][3] - nm1);
                    ps0 += s[mt][nt][0] + s[mt][nt][1];
                    ps1 += s[mt][nt][2] + s[mt][nt][3];
                }
                lrow[mt][0] = lrow[mt][0] * sc0 + ps0;
                lrow[mt][1] = lrow[mt][1] * sc1 + ps1;
                #pragma unroll
                for (int dt = 0; dt < 8; dt++) {
                    Ov[mt][dt][0] *= sc0; Ov[mt][dt][1] *= sc0;
                    Ov[mt][dt][2] *= sc1; Ov[mt][dt][3] *= sc1;
                }
            }

            #pragma unroll
            for (int g = 0; g < 8; g++) {
                uint32_t a[2][4];
                #pragma unroll
                for (int mt = 0; mt < 2; mt++) {
                    uint32_t p0 = f2tf(s[mt][g][0]), p1 = f2tf(s[mt][g][1]);
                    uint32_t p2 = f2tf(s[mt][g][2]), p3 = f2tf(s[mt][g][3]);
                    uint32_t t00 = __shfl_sync(0xffffffffu, p0, srcA);
                    uint32_t t01 = __shfl_sync(0xffffffffu, p1, srcA);
                    uint32_t t10 = __shfl_sync(0xffffffffu, p2, srcA);
                    uint32_t t11 = __shfl_sync(0xffffffffu, p3, srcA);
                    uint32_t u00 = __shfl_sync(0xffffffffu, p0, srcB);
                    uint32_t u01 = __shfl_sync(0xffffffffu, p1, srcB);
                    uint32_t u10 = __shfl_sync(0xffffffffu, p2, srcB);
                    uint32_t u11 = __shfl_sync(0xffffffffu, p3, srcB);
                    a[mt][0] = odd ? t01 : t00;
                    a[mt][1] = odd ? t11 : t10;
                    a[mt][2] = odd ? u01 : u00;
                    a[mt][3] = odd ? u11 : u10;
                }
                #pragma unroll
                for (int dt = 0; dt < 8; dt++) {
                    uint32_t bf[2];
                    bf[0] = Vs[jl + g * 8 + qd][dt * 8 + row];
                    bf[1] = Vs[jl + g * 8 + 4 + qd][dt * 8 + row];
                    mma8(Ov[0][dt], a[0], bf);
                    mma8(Ov[1][dt], a[1], bf);
                }
            }
        }
    }

    #pragma unroll
    for (int mt = 0; mt < 2; mt++) {
        float l0 = lrow[mt][0], l1 = lrow[mt][1];
        l0 += __shfl_xor_sync(0xffffffffu, l0, 1);
        l0 += __shfl_xor_sync(0xffffffffu, l0, 2);
        l1 += __shfl_xor_sync(0xffffffffu, l1, 1);
        l1 += __shfl_xor_sync(0xffffffffu, l1, 2);
        float inv0 = 1.0f / l0, inv1 = 1.0f / l1;
        #pragma unroll
        for (int dt = 0; dt < 8; dt++) {
            int d = n * DH + dt * 8 + 2 * qd;
            *(float2*)&av[(size_t)(irow[mt] * 2 + b) * NHD + d] =
                make_float2(Ov[mt][dt][0] * inv0, Ov[mt][dt][1] * inv0);
            *(float2*)&av[(size_t)((irow[mt] + 8) * 2 + b) * NHD + d] =
                make_float2(Ov[mt][dt][2] * inv1, Ov[mt][dt][3] * inv1);
        }
    }
}

// ---------------------------------------------------------------------------
extern "C" void kernel_launch(void* const* d_in, const int* in_sizes, int n_in,
                              void* d_out, int out_size)
{
    const float* w   = (const float*)d_in[0];
    const float* r   = (const float*)d_in[1];
    const float* rwb = (const float*)d_in[2];
    const float* rrb = (const float*)d_in[3];
    const float* Wq  = (const float*)d_in[4];
    const float* Wkv = (const float*)d_in[5];
    const float* Wr  = (const float*)d_in[6];
    const float* Wo  = (const float*)d_in[7];
    float* out = (float*)d_out;

    float *qh, *kv, *rk, *bd, *av;
    cudaGetSymbolAddress((void**)&qh, g_qh);
    cudaGetSymbolAddress((void**)&kv, g_kv);
    cudaGetSymbolAddress((void**)&rk, g_rk);
    cudaGetSymbolAddress((void**)&bd, g_bd);
    cudaGetSymbolAddress((void**)&av, g_av);

    static cudaStream_t st1 = 0, st2 = 0;
    static cudaEvent_t ev0 = 0, evKV = 0, evR = 0;
    if (!st1) {
        cudaStreamCreateWithFlags(&st1, cudaStreamNonBlocking);
        cudaStreamCreateWithFlags(&st2, cudaStreamNonBlocking);
        cudaEventCreateWithFlags(&ev0,  cudaEventDisableTiming);
        cudaEventCreateWithFlags(&evKV, cudaEventDisableTiming);
        cudaEventCreateWithFlags(&evR,  cudaEventDisableTiming);
        cudaFuncSetAttribute(scores_bd_tf32,
                             cudaFuncAttributeMaxDynamicSharedMemorySize,
                             2 * 128 * 68 * 4);
        cudaFuncSetAttribute(attn_fused,
                             cudaFuncAttributeMaxDynamicSharedMemorySize,
                             (128 * 68 + 128 * 72) * 4);
    }
    const int score_smem = 2 * 128 * 68 * 4;
    const int fused_smem = (128 * 68 + 128 * 72) * 4;

    cudaEventRecord(ev0, 0);
    cudaStreamWaitEvent(st1, ev0, 0);
    cudaStreamWaitEvent(st2, ev0, 0);

    // stream 0: Wq projection
    gemm_tf32<<<dim3(1024 / 128, 2048 / 128), 256, 0, 0>>>(
        w + (size_t)QLEN * BSZ * DM, Wq, qh, 2048, 1024, 1024);

    // st1: Wkv projection (largest, overlapped)
    gemm_tf32<<<dim3(2048 / 128, 4096 / 128), 256, 0, st1>>>(
        w, Wkv, kv, 4096, 2048, 1024);
    cudaEventRecord(evKV, st1);

    // st2: zero diag + Wr projection
    zero_diag<<<32, 1024, 0, st2>>>(bd);
    gemm_tf32<<<dim3(1024 / 128, 2048 / 128), 256, 0, st2>>>(
        r, Wr, rk, 2048, 1024, 1024);
    cudaEventRecord(evR, st2);

    // stream 0: BD scores
    cudaStreamWaitEvent(0, evR, 0);
    scores_bd_tf32<<<dim3(RLEN / 128, QLEN / 128, 32), 256, score_smem, 0>>>(
        qh, rk, rrb, bd);

    // stream 0: fused attention
    cudaStreamWaitEvent(0, evKV, 0);
    attn_fused<<<dim3(QLEN / 128, BSZ * NH), 128, fused_smem, 0>>>(
        qh, kv, bd, rwb, av);

    // output projection
    gemm_tf32<<<dim3(1024 / 128, 2048 / 128), 256, 0, 0>>>(
        av, Wo, out, 2048, 1024, 1024);
}